// round 2
// baseline (speedup 1.0000x reference)
#include <cuda_runtime.h>
#include <cuda_fp16.h>
#include <cstdint>

#define VOCABSZ 32000
#define EMBD    1024
#define HID     1024
#define G4      4096
#define NB      64
#define LSEQ    512
#define NCTA    128

// ---------------- device scratch (static; no cudaMalloc allowed) ----------------
__device__ __half g_Eb[(size_t)VOCABSZ * EMBD];          // E as fp16 (64 MB)
__device__ __half g_Bx[(size_t)G4 * 1024];               // W_x^T, [colp][k], gate-permuted (8 MB)
__device__ float  g_bias[G4];                            // permuted bias
__device__ float  g_Gx[(size_t)LSEQ * G4 * NB];          // precomputed x-gates, [t][cta][n][loc] (512 MB)
__device__ __half g_Hbuf[2][NB * HID];                   // H double buffer (fp16)
__device__ int    g_bar[LSEQ];                           // per-step grid-barrier counters

// gate-column permutation: colp = cta*32 + loc ; loc>>3 = gate (i,f,o,g), loc&7 = unit-in-cta
__device__ __forceinline__ int perm_row(int colp) {
    int cta = colp >> 5, loc = colp & 31;
    return ((loc >> 3) << 10) + (cta << 3) + (loc & 7);
}

// ---------------- mma / ldmatrix / cp.async helpers -----------------------------
__device__ __forceinline__ unsigned smem_u32(const void* p) {
    return (unsigned)__cvta_generic_to_shared(p);
}
__device__ __forceinline__ void ldmatrix_x4(unsigned* r, unsigned addr) {
    asm volatile("ldmatrix.sync.aligned.m8n8.x4.shared.b16 {%0,%1,%2,%3}, [%4];"
                 : "=r"(r[0]), "=r"(r[1]), "=r"(r[2]), "=r"(r[3]) : "r"(addr));
}
__device__ __forceinline__ void ldmatrix_x2(unsigned* r, unsigned addr) {
    asm volatile("ldmatrix.sync.aligned.m8n8.x2.shared.b16 {%0,%1}, [%2];"
                 : "=r"(r[0]), "=r"(r[1]) : "r"(addr));
}
__device__ __forceinline__ void mma16816(float* d, const unsigned* a, unsigned b0, unsigned b1) {
    asm volatile("mma.sync.aligned.m16n8k16.row.col.f32.f16.f16.f32 "
                 "{%0,%1,%2,%3}, {%4,%5,%6,%7}, {%8,%9}, {%0,%1,%2,%3};"
                 : "+f"(d[0]), "+f"(d[1]), "+f"(d[2]), "+f"(d[3])
                 : "r"(a[0]), "r"(a[1]), "r"(a[2]), "r"(a[3]), "r"(b0), "r"(b1));
}
__device__ __forceinline__ void cp16(void* s, const void* g) {
    asm volatile("cp.async.cg.shared.global [%0], [%1], 16;"
                 :: "r"(smem_u32(s)), "l"(g) : "memory");
}
__device__ __forceinline__ void cp_commit() { asm volatile("cp.async.commit_group;" ::: "memory"); }
template <int N>
__device__ __forceinline__ void cp_wait() { asm volatile("cp.async.wait_group %0;" :: "n"(N) : "memory"); }

__device__ __forceinline__ float sigf(float x) { return 1.0f / (1.0f + expf(-x)); }

// ---------------- prep: E -> fp16 ------------------------------------------------
__global__ __launch_bounds__(256) void k_cvt_e(const float* __restrict__ E) {
    size_t total8 = (size_t)VOCABSZ * EMBD / 8;
    size_t stride = (size_t)gridDim.x * blockDim.x;
    for (size_t i = (size_t)blockIdx.x * blockDim.x + threadIdx.x; i < total8; i += stride) {
        const float4* s = (const float4*)(E + i * 8);
        float4 v0 = s[0], v1 = s[1];
        __half2 h0 = __floats2half2_rn(v0.x, v0.y);
        __half2 h1 = __floats2half2_rn(v0.z, v0.w);
        __half2 h2 = __floats2half2_rn(v1.x, v1.y);
        __half2 h3 = __floats2half2_rn(v1.z, v1.w);
        uint4 o;
        o.x = *(unsigned*)&h0; o.y = *(unsigned*)&h1;
        o.z = *(unsigned*)&h2; o.w = *(unsigned*)&h3;
        ((uint4*)g_Eb)[i] = o;
    }
}

// ---------------- prep: pack Bx, bias, reset barriers & H0 -----------------------
__global__ __launch_bounds__(256) void k_pack(const float* __restrict__ W,
                                              const float* __restrict__ Wb) {
    int i0 = blockIdx.x * blockDim.x + threadIdx.x;
    int stride = gridDim.x * blockDim.x;
    for (int idx = i0; idx < G4 * 1024; idx += stride) {
        int colp = idx >> 10, k = idx & 1023;
        g_Bx[idx] = __float2half(W[(size_t)perm_row(colp) * 2048 + 1024 + k]);
    }
    for (int idx = i0; idx < G4; idx += stride) g_bias[idx] = Wb[perm_row(idx)];
    for (int idx = i0; idx < LSEQ; idx += stride) g_bar[idx] = 0;
    for (int idx = i0; idx < NB * HID; idx += stride) g_Hbuf[0][idx] = __float2half(0.0f);
}

// ---------------- phase 1: Gx = embed(X) @ Wx^T + b ------------------------------
// CTA tile 128(m) x 128(n), k-chunks of 32. 8 warps: wm in 0..3 (M=32), wn in 0..1 (N=64).
__global__ __launch_bounds__(256) void k_gx(const int* __restrict__ X) {
    __shared__ __align__(16) __half As[128][40];   // +8 halves pad: ldmatrix conflict-free
    __shared__ __align__(16) __half Bs[128][40];
    __shared__ int   toks[128];
    __shared__ float bsm[128];

    int tid = threadIdx.x, lane = tid & 31, warp = tid >> 5;
    int wm = warp >> 1, wn = warp & 1;
    int mblk = blockIdx.y * 128, nblk = blockIdx.x * 128;

    if (tid < 128) {
        int m = mblk + tid;                      // m = t*64 + n
        toks[tid] = X[(m & 63) * LSEQ + (m >> 6)];
        bsm[tid] = g_bias[nblk + tid];
    }

    float acc[2][8][4];
#pragma unroll
    for (int a = 0; a < 2; ++a)
#pragma unroll
        for (int b = 0; b < 8; ++b)
#pragma unroll
            for (int c = 0; c < 4; ++c) acc[a][b][c] = 0.0f;

    for (int kc = 0; kc < 32; ++kc) {
        int k0 = kc * 32;
        __syncthreads();
#pragma unroll
        for (int r = 0; r < 2; ++r) {            // A: 128 rows x 32 halves
            int idx = tid + r * 256;
            int row = idx >> 2, q = idx & 3;
            *(uint4*)&As[row][q * 8] =
                *(const uint4*)&g_Eb[(size_t)toks[row] * EMBD + k0 + q * 8];
        }
#pragma unroll
        for (int r = 0; r < 2; ++r) {            // B: 128 colp-rows x 32 halves
            int idx = tid + r * 256;
            int row = idx >> 2, q = idx & 3;
            *(uint4*)&Bs[row][q * 8] =
                *(const uint4*)&g_Bx[(size_t)(nblk + row) * 1024 + k0 + q * 8];
        }
        __syncthreads();
#pragma unroll
        for (int ks = 0; ks < 2; ++ks) {
            unsigned a[2][4];
#pragma unroll
            for (int mt = 0; mt < 2; ++mt)
                ldmatrix_x4(a[mt], smem_u32(&As[wm * 32 + mt * 16 + (lane & 15)]
                                              [ks * 16 + (lane >> 4) * 8]));
#pragma unroll
            for (int nt = 0; nt < 8; ++nt) {
                unsigned b[2];
                ldmatrix_x2(b, smem_u32(&Bs[wn * 64 + nt * 8 + (lane & 7)]
                                          [ks * 16 + ((lane >> 3) & 1) * 8]));
                mma16816(acc[0][nt], a[0], b[0], b[1]);
                mma16816(acc[1][nt], a[1], b[0], b[1]);
            }
        }
    }

    // epilogue: add bias, store permuted Gx[t][cta][n][loc]
#pragma unroll
    for (int mt = 0; mt < 2; ++mt) {
#pragma unroll
        for (int nt = 0; nt < 8; ++nt) {
            int mrow = mblk + wm * 32 + mt * 16 + (lane >> 2);
            int cloc = wn * 64 + nt * 8 + ((lane & 3) << 1);
            int colp = nblk + cloc;
            float b0 = bsm[cloc], b1 = bsm[cloc + 1];
            const float* c = acc[mt][nt];
#pragma unroll
            for (int rr = 0; rr < 2; ++rr) {
                int m = mrow + rr * 8;
                int t = m >> 6, n = m & 63;
                size_t off = (((size_t)t * NCTA + (colp >> 5)) * NB + n) * 32 + (colp & 31);
                float2 v; v.x = c[rr * 2] + b0; v.y = c[rr * 2 + 1] + b1;
                *(float2*)&g_Gx[off] = v;
            }
        }
    }
}

// ---------------- phase 2: persistent recurrent kernel ---------------------------
// 128 CTAs x 256 threads, each CTA owns 8 hidden units (32 gate columns).
// SMEM: Hs[64][1032]h, Ws[32][1032]h, gates[64][32]f, C[512]f  = 208384 B
#define HS_STRIDE 1032
#define SM_HS 0
#define SM_WS (64 * HS_STRIDE * 2)
#define SM_GT (SM_WS + 32 * HS_STRIDE * 2)
#define SM_C  (SM_GT + 64 * 32 * 4)
#define SMEM_REC (SM_C + 512 * 4)

__global__ void __launch_bounds__(256, 1) k_rec(const float* __restrict__ W,
                                                float* __restrict__ out) {
    extern __shared__ __align__(16) char smem[];
    __half (*Hs)[HS_STRIDE] = (__half(*)[HS_STRIDE])(smem + SM_HS);
    __half (*Ws)[HS_STRIDE] = (__half(*)[HS_STRIDE])(smem + SM_WS);
    float (*gsm)[32]        = (float(*)[32])(smem + SM_GT);
    float* Cs               = (float*)(smem + SM_C);

    int cta = blockIdx.x;
    int tid = threadIdx.x, lane = tid & 31, warp = tid >> 5;
    int wm = warp & 3, wn = warp >> 2;   // wm: m-tile 0..3 (16 rows), wn: 0..1 (16 gate cols)

    // resident weight slice: Ws[nloc][k] = W[perm(cta*32+nloc)][k]  (h-part, cols 0..1023)
    for (int idx = tid; idx < 32 * 1024; idx += 256) {
        int nloc = idx >> 10, k = idx & 1023;
        int wrow = ((nloc >> 3) << 10) + (cta << 3) + (nloc & 7);
        Ws[nloc][k] = __float2half(W[(size_t)wrow * 2048 + k]);
    }
    for (int idx = tid; idx < 512; idx += 256) Cs[idx] = 0.0f;
    __syncthreads();

    for (int t = 0; t < LSEQ; ++t) {
        const __half* Hg = g_Hbuf[t & 1];

        // stage H in two K-halves via cp.async (L2-direct; half1 overlaps half0 compute)
#pragma unroll
        for (int h = 0; h < 2; ++h) {
#pragma unroll
            for (int i = 0; i < 16; ++i) {
                int idx = tid + i * 256;          // 0..4095
                int row = idx >> 6, c16 = idx & 63;
                cp16(&Hs[row][h * 512 + c16 * 8], Hg + row * 1024 + h * 512 + c16 * 8);
            }
            cp_commit();
        }

        float acc0[4] = {0, 0, 0, 0}, acc1[4] = {0, 0, 0, 0};

        cp_wait<1>();
        __syncthreads();
#pragma unroll 8
        for (int kt = 0; kt < 32; ++kt) {
            unsigned a[4], b0[2], b1[2];
            ldmatrix_x4(a, smem_u32(&Hs[wm * 16 + (lane & 15)][kt * 16 + (lane >> 4) * 8]));
            ldmatrix_x2(b0, smem_u32(&Ws[wn * 16 + (lane & 7)][kt * 16 + ((lane >> 3) & 1) * 8]));
            ldmatrix_x2(b1, smem_u32(&Ws[wn * 16 + 8 + (lane & 7)][kt * 16 + ((lane >> 3) & 1) * 8]));
            mma16816(acc0, a, b0[0], b0[1]);
            mma16816(acc1, a, b1[0], b1[1]);
        }
        cp_wait<0>();
        __syncthreads();
#pragma unroll 8
        for (int kt = 32; kt < 64; ++kt) {
            unsigned a[4], b0[2], b1[2];
            ldmatrix_x4(a, smem_u32(&Hs[wm * 16 + (lane & 15)][kt * 16 + (lane >> 4) * 8]));
            ldmatrix_x2(b0, smem_u32(&Ws[wn * 16 + (lane & 7)][kt * 16 + ((lane >> 3) & 1) * 8]));
            ldmatrix_x2(b1, smem_u32(&Ws[wn * 16 + 8 + (lane & 7)][kt * 16 + ((lane >> 3) & 1) * 8]));
            mma16816(acc0, a, b0[0], b0[1]);
            mma16816(acc1, a, b1[0], b1[1]);
        }

        // write gates to SMEM exchange buffer
        {
            int m = wm * 16 + (lane >> 2);
            int cl = wn * 16 + ((lane & 3) << 1);
            gsm[m][cl] = acc0[0];     gsm[m][cl + 1] = acc0[1];
            gsm[m + 8][cl] = acc0[2]; gsm[m + 8][cl + 1] = acc0[3];
            gsm[m][cl + 8] = acc1[0];     gsm[m][cl + 9] = acc1[1];
            gsm[m + 8][cl + 8] = acc1[2]; gsm[m + 8][cl + 9] = acc1[3];
        }
        __syncthreads();

        // elementwise LSTM update for this CTA's 8 units x 64 batch
        const float* gx = g_Gx + ((size_t)t * NCTA + cta) * NB * 32;
        __half* Hn = g_Hbuf[(t & 1) ^ 1];
#pragma unroll
        for (int p = tid; p < 512; p += 256) {
            int m = p >> 3, j = p & 7;
            float vi = gsm[m][j]      + gx[m * 32 + j];
            float vf = gsm[m][8 + j]  + gx[m * 32 + 8 + j];
            float vo = gsm[m][16 + j] + gx[m * 32 + 16 + j];
            float vg = gsm[m][24 + j] + gx[m * 32 + 24 + j];
            float ig = sigf(vi), fg = sigf(vf), og = sigf(vo), gg = tanhf(vg);
            float C = fg * Cs[p] + ig * gg;
            Cs[p] = C;
            float hval = og * tanhf(C);
            int col = (cta << 3) + j;
            Hn[m * 1024 + col] = __float2half(hval);
            if (t == LSEQ - 1) out[m * 1024 + col] = hval;
        }

        // grid barrier (release: threadfence+atomic; acquire: L2 poll; all loads are L2-path)
        __threadfence();
        __syncthreads();
        if (tid == 0) {
            atomicAdd(&g_bar[t], 1);
            while (*(volatile int*)&g_bar[t] < NCTA) { }
        }
        __syncthreads();
    }
}

// ---------------- launch ----------------------------------------------------------
extern "C" void kernel_launch(void* const* d_in, const int* in_sizes, int n_in,
                              void* d_out, int out_size) {
    (void)in_sizes; (void)n_in; (void)out_size;
    const int*   X  = (const int*)d_in[0];
    const float* E  = (const float*)d_in[1];
    const float* W  = (const float*)d_in[2];
    const float* Wb = (const float*)d_in[3];
    float* out = (float*)d_out;

    cudaFuncSetAttribute(k_rec, cudaFuncAttributeMaxDynamicSharedMemorySize, SMEM_REC);

    k_cvt_e<<<2048, 256>>>(E);
    k_pack<<<1024, 256>>>(W, Wb);
    k_gx<<<dim3(32, 256), 256>>>(X);
    k_rec<<<NCTA, 256, SMEM_REC>>>(W, out);
}